// round 2
// baseline (speedup 1.0000x reference)
#include <cuda_runtime.h>
#include <math.h>

#define BQ   2048
#define NST  65536
#define HD   1024
#define TOPK 8
#define NCAND 16

// ---------------- scratch (static device globals; no runtime allocation) ----------------
__device__ float  g_WkT[HD * HD];
__device__ float  g_WvT[HD * HD];
__device__ float  g_WoT[HD * HD];
__device__ float  g_storeT[(size_t)HD * NST];        // 256 MB
__device__ float  g_keys[(size_t)NST * HD];          // 256 MB
__device__ float  g_scores[(size_t)BQ * NST];        // 512 MB
__device__ float  g_qk[BQ * HD];
__device__ float  g_qinvf[BQ];
__device__ double g_qinvd[BQ];
__device__ double g_wd[NST];
__device__ double g_kinvd[NST];
__device__ float  g_cf[NST];
__device__ double g_partiald[256];
__device__ double g_Sd[1];
__device__ int    g_cand[BQ * NCAND];
__device__ float  g_attn[BQ * TOPK];
__device__ int    g_topi[BQ * TOPK];
__device__ float  g_u[BQ * HD];
__device__ float  g_t[BQ * HD];

// ---------------- transpose (dims multiples of 32) ----------------
__global__ void transpose_kernel(const float* __restrict__ in, float* __restrict__ out,
                                 int rows, int cols) {
    __shared__ float tile[32][33];
    int x0 = blockIdx.x * 32;
    int y0 = blockIdx.y * 32;
    int tx = threadIdx.x, ty = threadIdx.y;
    #pragma unroll
    for (int r = ty; r < 32; r += 8)
        tile[r][tx] = in[(size_t)(y0 + r) * cols + (x0 + tx)];
    __syncthreads();
    #pragma unroll
    for (int r = ty; r < 32; r += 8)
        out[(size_t)(x0 + r) * rows + (y0 + tx)] = tile[tx][r];
}

// ---------------- weights in fp64 + partial sums ----------------
__global__ void weight_partial_kernel(const float* __restrict__ imp,
                                      const float* __restrict__ ts,
                                      double* __restrict__ wd,
                                      double* __restrict__ partial) {
    __shared__ double sm[256];
    int j = blockIdx.x * 256 + threadIdx.x;
    double age = 1.0 - (double)ts[j];
    double r = exp(-fabs(age) * 0.01);
    double wv = r * ((double)imp[j] + 1.0);
    wd[j] = wv;
    sm[threadIdx.x] = wv;
    __syncthreads();
    for (int s = 128; s > 0; s >>= 1) {
        if (threadIdx.x < s) sm[threadIdx.x] += sm[threadIdx.x + s];
        __syncthreads();
    }
    if (threadIdx.x == 0) partial[blockIdx.x] = sm[0];
}

__global__ void weight_sum_kernel(const double* __restrict__ partial, double* __restrict__ S) {
    __shared__ double sm[256];
    sm[threadIdx.x] = partial[threadIdx.x];
    __syncthreads();
    for (int s = 128; s > 0; s >>= 1) {
        if (threadIdx.x < s) sm[threadIdx.x] += sm[threadIdx.x + s];
        __syncthreads();
    }
    if (threadIdx.x == 0) S[0] = sm[0] + 1e-8;
}

// ---------------- per-row 1/max(||q||, eps) in fp64 ----------------
__global__ void qinv_kernel(const float* __restrict__ q,
                            float* __restrict__ qinvf, double* __restrict__ qinvd) {
    __shared__ double sm[128];
    int b = blockIdx.x;
    const float* row = q + (size_t)b * HD;
    double acc = 0.0;
    for (int h = threadIdx.x; h < HD; h += 128) { double v = row[h]; acc += v * v; }
    sm[threadIdx.x] = acc;
    __syncthreads();
    for (int s = 64; s > 0; s >>= 1) {
        if (threadIdx.x < s) sm[threadIdx.x] += sm[threadIdx.x + s];
        __syncthreads();
    }
    if (threadIdx.x == 0) {
        double n = sqrt(sm[0]);
        double inv = 1.0 / fmax(n, 1e-12);
        qinvd[b] = inv;
        qinvf[b] = (float)inv;
    }
}

// ---------------- key norms (fp64) + screening column scale ----------------
__global__ void cscale_kernel(const float* __restrict__ keys, const double* __restrict__ wd,
                              const double* __restrict__ S,
                              double* __restrict__ kinvd, float* __restrict__ cf) {
    __shared__ double sm[128];
    int j = blockIdx.x;
    const float* row = keys + (size_t)j * HD;
    double acc = 0.0;
    for (int h = threadIdx.x; h < HD; h += 128) { double v = row[h]; acc += v * v; }
    sm[threadIdx.x] = acc;
    __syncthreads();
    for (int s = 64; s > 0; s >>= 1) {
        if (threadIdx.x < s) sm[threadIdx.x] += sm[threadIdx.x + s];
        __syncthreads();
    }
    if (threadIdx.x == 0) {
        double n = sqrt(sm[0]);
        double inv = 1.0 / fmax(n, 1e-12);
        kinvd[j] = inv;
        cf[j] = (float)(wd[j] / S[0] * inv);
    }
}

// ---------------- generic SGEMM: C[M,Nn] = A[M,Kk] @ B[Kk,Nn] ----------------
__global__ __launch_bounds__(256) void sgemm_kernel(
    const float* __restrict__ A, const float* __restrict__ Bm, float* __restrict__ C,
    int M, int Nn, int Kk,
    const float* __restrict__ rowScale, const float* __restrict__ colScale) {
    __shared__ float As[8][128];
    __shared__ float Bs[8][128];
    const int tid  = threadIdx.x;
    const int crow = blockIdx.y * 128;
    const int ccol = blockIdx.x * 128;
    const int tr = (tid / 16) * 8;
    const int tc = (tid % 16) * 8;
    const int aRow = tid >> 1, aCol = (tid & 1) * 4;
    const int bRow = tid >> 5, bCol = (tid & 31) * 4;
    const float* Ag = A + (size_t)(crow + aRow) * Kk + aCol;
    const float* Bg = Bm + (size_t)bRow * Nn + ccol + bCol;

    float acc[8][8];
    #pragma unroll
    for (int i = 0; i < 8; i++)
        #pragma unroll
        for (int j = 0; j < 8; j++) acc[i][j] = 0.0f;

    for (int k0 = 0; k0 < Kk; k0 += 8) {
        float4 av = *(const float4*)(Ag + k0);
        As[aCol + 0][aRow] = av.x;
        As[aCol + 1][aRow] = av.y;
        As[aCol + 2][aRow] = av.z;
        As[aCol + 3][aRow] = av.w;
        float4 bv = *(const float4*)(Bg + (size_t)k0 * Nn);
        *(float4*)(&Bs[bRow][bCol]) = bv;
        __syncthreads();
        #pragma unroll
        for (int k = 0; k < 8; k++) {
            float ar[8], br[8];
            *(float4*)(ar)     = *(const float4*)(&As[k][tr]);
            *(float4*)(ar + 4) = *(const float4*)(&As[k][tr + 4]);
            *(float4*)(br)     = *(const float4*)(&Bs[k][tc]);
            *(float4*)(br + 4) = *(const float4*)(&Bs[k][tc + 4]);
            #pragma unroll
            for (int i = 0; i < 8; i++)
                #pragma unroll
                for (int j = 0; j < 8; j++)
                    acc[i][j] += ar[i] * br[j];
        }
        __syncthreads();
    }

    #pragma unroll
    for (int i = 0; i < 8; i++) {
        float rs = rowScale ? rowScale[crow + tr + i] : 1.0f;
        float v[8];
        #pragma unroll
        for (int j = 0; j < 8; j++) {
            v[j] = acc[i][j] * rs;
            if (colScale) v[j] *= colScale[ccol + tc + j];
        }
        float* Crow = C + (size_t)(crow + tr + i) * Nn + ccol + tc;
        *(float4*)(Crow)     = *(float4*)(v);
        *(float4*)(Crow + 4) = *(float4*)(v + 4);
    }
}

// ---------------- top-16 screening per row (ties -> lower index) ----------------
__device__ __forceinline__ bool better(float v1, int i1, float v2, int i2) {
    return (v1 > v2) || (v1 == v2 && i1 < i2);
}

__global__ __launch_bounds__(256) void screen_kernel(const float* __restrict__ S,
                                                     int* __restrict__ cand) {
    __shared__ float sv[256 * NCAND];
    __shared__ int   si[256 * NCAND];
    int b = blockIdx.x;
    const float* row = S + (size_t)b * NST;
    float lv[NCAND]; int li[NCAND];
    #pragma unroll
    for (int k = 0; k < NCAND; k++) { lv[k] = -1e30f; li[k] = 0x7fffffff; }
    for (int j = threadIdx.x; j < NST; j += 256) {
        float v = row[j];
        if (better(v, j, lv[NCAND - 1], li[NCAND - 1])) {
            int p = NCAND - 1;
            while (p > 0 && better(v, j, lv[p - 1], li[p - 1])) {
                lv[p] = lv[p - 1]; li[p] = li[p - 1]; p--;
            }
            lv[p] = v; li[p] = j;
        }
    }
    #pragma unroll
    for (int k = 0; k < NCAND; k++) {
        sv[threadIdx.x * NCAND + k] = lv[k];
        si[threadIdx.x * NCAND + k] = li[k];
    }
    __syncthreads();
    for (int s = 128; s > 0; s >>= 1) {
        if (threadIdx.x < s) {
            float* pa  = &sv[threadIdx.x * NCAND];
            int*   pai = &si[threadIdx.x * NCAND];
            float* pb  = &sv[(threadIdx.x + s) * NCAND];
            int*   pbi = &si[(threadIdx.x + s) * NCAND];
            float mv[NCAND]; int mi[NCAND];
            int ia = 0, ib = 0;
            #pragma unroll
            for (int k = 0; k < NCAND; k++) {
                bool takeA = (ib >= NCAND) ||
                             (ia < NCAND && better(pa[ia], pai[ia], pb[ib], pbi[ib]));
                if (takeA) { mv[k] = pa[ia]; mi[k] = pai[ia]; ia++; }
                else       { mv[k] = pb[ib]; mi[k] = pbi[ib]; ib++; }
            }
            #pragma unroll
            for (int k = 0; k < NCAND; k++) { pa[k] = mv[k]; pai[k] = mi[k]; }
        }
        __syncthreads();
    }
    if (threadIdx.x < NCAND) cand[b * NCAND + threadIdx.x] = si[threadIdx.x];
}

// ---------------- exact fp64 rescore of 16 candidates + top-8 + softmax ----------------
__global__ __launch_bounds__(512) void rescore_kernel(
    const float* __restrict__ q, const float* __restrict__ keys,
    const int* __restrict__ cand,
    const double* __restrict__ qinvd, const double* __restrict__ kinvd,
    const double* __restrict__ wd, const double* __restrict__ Sd,
    float* __restrict__ attn, int* __restrict__ topi) {
    __shared__ double ssim[NCAND];
    __shared__ int    sidx[NCAND];
    int b = blockIdx.x;
    int wid = threadIdx.x / 32;
    int lid = threadIdx.x % 32;

    int ci = cand[b * NCAND + wid];
    const float* qrow = q + (size_t)b * HD;
    const float* krow = keys + (size_t)ci * HD;
    double acc = 0.0;
    #pragma unroll
    for (int it = 0; it < HD / 32; it++) {
        int h = it * 32 + lid;
        acc += (double)qrow[h] * (double)krow[h];
    }
    #pragma unroll
    for (int off = 16; off > 0; off >>= 1)
        acc += __shfl_down_sync(0xffffffffu, acc, off);
    if (lid == 0) {
        ssim[wid] = acc * qinvd[b] * kinvd[ci] * (wd[ci] / Sd[0]);
        sidx[wid] = ci;
    }
    __syncthreads();

    if (threadIdx.x == 0) {
        double v[NCAND]; int ix[NCAND]; bool used[NCAND];
        #pragma unroll
        for (int k = 0; k < NCAND; k++) { v[k] = ssim[k]; ix[k] = sidx[k]; used[k] = false; }
        double tv[TOPK]; int ti[TOPK];
        for (int k = 0; k < TOPK; k++) {
            int best = -1;
            for (int m = 0; m < NCAND; m++) {
                if (used[m]) continue;
                if (best < 0 || v[m] > v[best] || (v[m] == v[best] && ix[m] < ix[best]))
                    best = m;
            }
            used[best] = true;
            tv[k] = v[best]; ti[k] = ix[best];
        }
        double mx = tv[0];
        for (int k = 1; k < TOPK; k++) mx = fmax(mx, tv[k]);
        double e[TOPK], s = 0.0;
        for (int k = 0; k < TOPK; k++) { e[k] = exp(tv[k] - mx); s += e[k]; }
        double inv = 1.0 / s;
        for (int k = 0; k < TOPK; k++) {
            attn[b * TOPK + k] = (float)(e[k] * inv);
            topi[b * TOPK + k] = ti[k];
        }
    }
}

// ---------------- combine: u_b = sum_k attn * store[idx] ----------------
__global__ void combine_kernel(const float* __restrict__ attn, const int* __restrict__ topi,
                               const float* __restrict__ store, float* __restrict__ u) {
    int b = blockIdx.x;
    float a[TOPK]; const float* rows[TOPK];
    #pragma unroll
    for (int k = 0; k < TOPK; k++) {
        a[k] = attn[b * TOPK + k];
        rows[k] = store + (size_t)topi[b * TOPK + k] * HD;
    }
    for (int h = threadIdx.x; h < HD; h += 128) {
        float acc = 0.0f;
        #pragma unroll
        for (int k = 0; k < TOPK; k++) acc += a[k] * rows[k][h];
        u[(size_t)b * HD + h] = acc;
    }
}

// ---------------- host launcher ----------------
extern "C" void kernel_launch(void* const* d_in, const int* in_sizes, int n_in,
                              void* d_out, int out_size) {
    const float* query      = (const float*)d_in[0];
    const float* store      = (const float*)d_in[1];
    const float* importance = (const float*)d_in[2];
    const float* timestamps = (const float*)d_in[3];
    const float* Wk         = (const float*)d_in[4];
    const float* Wv         = (const float*)d_in[5];
    const float* Wo         = (const float*)d_in[6];
    float* out = (float*)d_out;

    float *WkT, *WvT, *WoT, *storeT, *keys, *scores, *qk, *qinvf, *cf, *attn, *u, *t;
    double *qinvd, *wd, *kinvd, *partiald, *Sd;
    int *cand, *topi;
    cudaGetSymbolAddress((void**)&WkT,     g_WkT);
    cudaGetSymbolAddress((void**)&WvT,     g_WvT);
    cudaGetSymbolAddress((void**)&WoT,     g_WoT);
    cudaGetSymbolAddress((void**)&storeT,  g_storeT);
    cudaGetSymbolAddress((void**)&keys,    g_keys);
    cudaGetSymbolAddress((void**)&scores,  g_scores);
    cudaGetSymbolAddress((void**)&qk,      g_qk);
    cudaGetSymbolAddress((void**)&qinvf,   g_qinvf);
    cudaGetSymbolAddress((void**)&qinvd,   g_qinvd);
    cudaGetSymbolAddress((void**)&wd,      g_wd);
    cudaGetSymbolAddress((void**)&kinvd,   g_kinvd);
    cudaGetSymbolAddress((void**)&cf,      g_cf);
    cudaGetSymbolAddress((void**)&partiald,g_partiald);
    cudaGetSymbolAddress((void**)&Sd,      g_Sd);
    cudaGetSymbolAddress((void**)&cand,    g_cand);
    cudaGetSymbolAddress((void**)&attn,    g_attn);
    cudaGetSymbolAddress((void**)&topi,    g_topi);
    cudaGetSymbolAddress((void**)&u,       g_u);
    cudaGetSymbolAddress((void**)&t,       g_t);

    dim3 tb(32, 8);
    transpose_kernel<<<dim3(HD / 32, HD / 32), tb>>>(Wk, WkT, HD, HD);
    transpose_kernel<<<dim3(HD / 32, HD / 32), tb>>>(Wv, WvT, HD, HD);
    transpose_kernel<<<dim3(HD / 32, HD / 32), tb>>>(Wo, WoT, HD, HD);
    transpose_kernel<<<dim3(HD / 32, NST / 32), tb>>>(store, storeT, NST, HD);

    weight_partial_kernel<<<256, 256>>>(importance, timestamps, wd, partiald);
    weight_sum_kernel<<<1, 256>>>(partiald, Sd);
    qinv_kernel<<<BQ, 128>>>(query, qinvf, qinvd);

    // keys = store @ Wk^T   [65536 x 1024]
    sgemm_kernel<<<dim3(HD / 128, NST / 128), 256>>>(store, WkT, keys, NST, HD, HD, nullptr, nullptr);
    cscale_kernel<<<NST, 128>>>(keys, wd, Sd, kinvd, cf);

    // qk = (query / ||q||) @ Wk   [2048 x 1024]
    sgemm_kernel<<<dim3(HD / 128, BQ / 128), 256>>>(query, Wk, qk, BQ, HD, HD, qinvf, nullptr);
    // screening scores = qk @ store^T, column-scaled   [2048 x 65536]
    sgemm_kernel<<<dim3(NST / 128, BQ / 128), 256>>>(qk, storeT, scores, BQ, NST, HD, nullptr, cf);

    screen_kernel<<<BQ, 256>>>(scores, cand);
    rescore_kernel<<<BQ, 512>>>(query, keys, cand, qinvd, kinvd, wd, Sd, attn, topi);
    combine_kernel<<<BQ, 128>>>(attn, topi, store, u);

    // t = u @ Wv^T ; out = t @ Wo^T
    sgemm_kernel<<<dim3(HD / 128, BQ / 128), 256>>>(u, WvT, t, BQ, HD, HD, nullptr, nullptr);
    sgemm_kernel<<<dim3(HD / 128, BQ / 128), 256>>>(t, WoT, out, BQ, HD, HD, nullptr, nullptr);
}